// round 15
// baseline (speedup 1.0000x reference)
#include <cuda_runtime.h>
#include <cuda_fp16.h>
#include <math.h>
#include <stdint.h>

// ---------------------------------------------------------------------------
// Scale_41523743817857 — fp16 mma.sync, nested-prefix im2col K-packing,
// M=256 macro-tile. Stages 1-4 build fp16 context; ctx2K-lite builds the
// im2col tensor CTX2[pixel][592] (ch2 = ch*9+tap nested-prefix order).
// Weights reordered likewise. Stage 5: one GEMM per (i, 256-px tile):
// M=256, N=128, K=ceil(9c/16)*16, 512 threads (16 warps: 8 m-slots x 2
// n-halves), 2-stage cp.async pipeline over 64-wide K stages, m16n8k16 fp16
// MMAs + fp32 accumulators. Epilogue: bias+relu+dense+d2s+affine fused.
// ---------------------------------------------------------------------------

#define CTX_H 66
#define CTX_W 66
#define CTX_C 64
#define K2    592          // padded im2col channel count (>= max Kp = 544)

__device__ float d_g[8 * 266 * 266 * 3];
__device__ float d_t1[8 * 128 * 266 * 3];
__device__ float d_kc[12];
__device__ __half d_ctxf[8 * CTX_H * CTX_W * CTX_C];   // fp16 padded context
__device__ __half d_ctx2[8 * 64 * 64 * K2];            // im2col, (ch*9+tap) order
__device__ __half d_w2[48 * 128 * K2];                 // weights, same order

#define SW128(o) ((o) ^ (((o) >> 3) & 0x70))

__device__ __forceinline__ uint32_t smem_to_u32(const void* p) {
    uint32_t a;
    asm("{ .reg .u64 t; cvta.to.shared.u64 t, %1; cvt.u32.u64 %0, t; }"
        : "=r"(a) : "l"(p));
    return a;
}
__device__ __forceinline__ void ldsm_x4(uint32_t* r, uint32_t addr) {
    asm volatile("ldmatrix.sync.aligned.m8n8.x4.shared.b16 {%0,%1,%2,%3}, [%4];"
        : "=r"(r[0]), "=r"(r[1]), "=r"(r[2]), "=r"(r[3]) : "r"(addr));
}
__device__ __forceinline__ void mma_f16(float* c, const uint32_t* a,
                                        const uint32_t* b) {
    asm volatile(
        "mma.sync.aligned.m16n8k16.row.col.f32.f16.f16.f32 "
        "{%0,%1,%2,%3}, {%4,%5,%6,%7}, {%8,%9}, {%0,%1,%2,%3};"
        : "+f"(c[0]), "+f"(c[1]), "+f"(c[2]), "+f"(c[3])
        : "r"(a[0]), "r"(a[1]), "r"(a[2]), "r"(a[3]), "r"(b[0]), "r"(b[1]));
}
#define CP_ASYNC16(dst, src) \
    asm volatile("cp.async.cg.shared.global [%0], [%1], 16;" \
        :: "r"(dst), "l"(src) : "memory")
#define CP_COMMIT() asm volatile("cp.async.commit_group;" ::: "memory")
#define CP_WAIT(n)  asm volatile("cp.async.wait_group %0;" :: "n"(n) : "memory")

// ======================= preprocessing kernels =============================
__global__ void initCoefsK() {
    if (threadIdx.x == 0 && blockIdx.x == 0) {
        double v[12]; double sum = 0.0;
        for (int t = 0; t < 12; t++) {
            double pos = ((double)t - 5.5) / 2.0;
            double a = sin(M_PI * pos) / (M_PI * pos);
            double p3 = pos / 3.0;
            double b = sin(M_PI * p3) / (M_PI * p3);
            double val = (double)((float)(a * b));
            v[t] = val; sum += val;
        }
        for (int t = 0; t < 12; t++) d_kc[t] = (float)(v[t] / sum);
    }
}
__global__ void gammaK(const float* __restrict__ x, int n) {
    int i = blockIdx.x * blockDim.x + threadIdx.x;
    if (i < n) d_g[i] = __powf(x[i], 2.2f);
}
__global__ void convHK() {
    const int n = 8 * 128 * 266 * 3;
    int idx = blockIdx.x * blockDim.x + threadIdx.x;
    if (idx >= n) return;
    float k[12];
#pragma unroll
    for (int t = 0; t < 12; t++) k[t] = d_kc[t];
    int ch = idx % 3;
    int w  = (idx / 3) % 266;
    int h  = (idx / (3 * 266)) % 128;
    int b  = idx / (3 * 266 * 128);
    const float* src = d_g + ((size_t)(b * 266 + 2 * h) * 266 + w) * 3 + ch;
    float s = 0.f;
#pragma unroll
    for (int t = 0; t < 12; t++) s += k[t] * src[(size_t)t * 266 * 3];
    d_t1[idx] = s;
}
__global__ void zeroCtxK() {
    const int n4 = (8 * CTX_H * CTX_W * CTX_C) / 4;
    int i = blockIdx.x * blockDim.x + threadIdx.x;
    if (i < n4) ((uint2*)d_ctxf)[i] = make_uint2(0u, 0u);
}
__global__ void convWK() {
    const int n = 8 * 128 * 128 * 3;
    int idx = blockIdx.x * blockDim.x + threadIdx.x;
    if (idx >= n) return;
    float k[12];
#pragma unroll
    for (int t = 0; t < 12; t++) k[t] = d_kc[t];
    int ch = idx % 3;
    int w2 = (idx / 3) % 128;
    int h  = (idx / (3 * 128)) % 128;
    int b  = idx / (3 * 128 * 128);
    const float* src = d_t1 + ((size_t)(b * 128 + h) * 266 + 2 * w2) * 3 + ch;
    float s = 0.f;
#pragma unroll
    for (int t = 0; t < 12; t++) s += k[t] * src[t * 3];
    float v = (s > 0.f) ? __powf(fmaxf(s, 1e-20f), (float)(1.0 / 2.2)) : 0.f;
    v = v * 2.f - 1.f;
    int yo = h >> 1, xo = w2 >> 1;
    int sub = ((h & 1) * 2 + (w2 & 1)) * 3 + ch;
    d_ctxf[(((size_t)b * CTX_H + 1 + yo) * CTX_W + 1 + xo) * CTX_C + sub] =
        __float2half_rn(v);
}
__global__ void exCropK(const float* __restrict__ ex) {
    const int n = 8 * 256 * 256 * 3;
    int idx = blockIdx.x * blockDim.x + threadIdx.x;
    if (idx >= n) return;
    int ch = idx % 3;
    int x  = (idx / 3) % 256;
    int y  = (idx / (3 * 256)) % 256;
    int b  = idx / (3 * 256 * 256);
    float v = ex[((size_t)(b * 266 + 5 + y) * 266 + (5 + x)) * 3 + ch] * 2.f - 1.f;
    int yo = y >> 2, xo = x >> 2;
    int sub = 12 + ((y & 3) * 4 + (x & 3)) * 3 + ch;
    d_ctxf[(((size_t)b * CTX_H + 1 + yo) * CTX_W + 1 + xo) * CTX_C + sub] =
        __float2half_rn(v);
}
// im2col lite: thread = (pixel, ch); 9 coalesced L2-cached gmem loads per
// thread, scatter into a per-pixel smem row buffer (writes only), then flush
// 4 complete 592-ch rows with coalesced uint4 stores. One smem hop.
#define SROW_STRIDE 600    // halves; 1200 B, 16B-aligned
__global__ __launch_bounds__(256) void ctx2K() {
    __shared__ __half srow[4 * SROW_STRIDE];
    const int tid = threadIdx.x;
    const int ch  = tid & 63;
    const int pl  = tid >> 6;               // 0..3
    const int pix = blockIdx.x * 4 + pl;
    const int x = pix & 63;
    const int y = (pix >> 6) & 63;
    const int b = pix >> 12;

    const __half* src =
        d_ctxf + (((size_t)b * CTX_H + y) * CTX_W + x) * CTX_C + ch;
    __half* dst = srow + pl * SROW_STRIDE + ch * 9;
#pragma unroll
    for (int ky = 0; ky < 3; ky++)
#pragma unroll
        for (int kx = 0; kx < 3; kx++)
            dst[ky * 3 + kx] = src[((size_t)ky * CTX_W + kx) * CTX_C];
    if (ch < 16)
        srow[pl * SROW_STRIDE + 576 + ch] = __ushort_as_half(0);
    __syncthreads();

    // flush: 4 rows x 74 uint4 (592 halves)
    for (int t = tid; t < 4 * 74; t += 256) {
        int p2 = t / 74;
        int q  = t - p2 * 74;
        *(uint4*)(d_ctx2 + ((size_t)(blockIdx.x * 4 + p2)) * K2 + q * 8) =
            *(const uint4*)(srow + p2 * SROW_STRIDE + q * 8);
    }
}
// weights: d_w2[i][n][ch2], ch2 = ch*9 + tap; zero for ch >= c or ch2 >= 576
__global__ void w2K(const float* __restrict__ Wc) {
    const size_t n = (size_t)48 * 128 * K2;
    size_t idx = (size_t)blockIdx.x * blockDim.x + threadIdx.x;
    if (idx >= n) return;
    int ch2 = (int)(idx % K2);
    int nn  = (int)((idx / K2) % 128);
    int i   = (int)(idx / ((size_t)K2 * 128));
    int c   = 12 + i;
    float v = 0.f;
    if (ch2 < 576) {
        int ch  = ch2 / 9;
        int tap = ch2 - ch * 9;
        if (ch < c)
            v = Wc[((((size_t)i * 3 + tap / 3) * 3 + (tap % 3)) * 59 + ch) * 128 + nn];
    }
    d_w2[idx] = __float2half_rn(v);
}

// ======================= main tensor-core kernel ===========================
// M=256 tile: SMEM = RED(1KB)/BCS/WDS then two 48KB stages of
// {A: 256x128B = 32KB, B: 128x128B = 16KB}.
#define SM_RED   0
#define SM_BCS   1024
#define SM_WDS   1536
#define SM_T0    2048
#define OFF_A    0
#define OFF_B    32768
#define STAGE_SZ 49152
#define SM_TOTAL (SM_T0 + 2 * STAGE_SZ)   // 100352 B

__global__ __launch_bounds__(512, 1) void predMmaK(
    const float* __restrict__ bc,   // (48,128)
    const float* __restrict__ Wd,   // (48,128)
    const float* __restrict__ bd,   // (48)
    float* __restrict__ out)        // (8,256,256,3)
{
    extern __shared__ char smem[];
    uint32_t sb = smem_to_u32(smem);
    const int tid = threadIdx.x;
    const int wid = tid >> 5;
    const int lid = tid & 31;

    const int i = blockIdx.y;
    const int c = 12 + i;
    const int Kp = ((9 * c + 15) >> 4) << 4;   // packed K, mult of 16
    const int nchunks = Kp >> 4;               // 7..34
    const int nstages = (nchunks + 3) >> 2;    // K=64 stages

    const int tile = blockIdx.x;               // b in [0,8), ty in [0,16)
    const int b  = tile >> 4;
    const int ty = tile & 15;
    const int y0 = ty * 4;                     // 4 rows of the 64x64 grid
    const size_t pixbase = (size_t)b * 4096 + (size_t)y0 * 64;  // 256 linear px

    if (tid < 128) {
        ((float*)(smem + SM_BCS))[tid] = bc[i * 128 + tid];
        ((float*)(smem + SM_WDS))[tid] = Wd[i * 128 + tid];
    }

    // tile-load roles: A row rA = tid>>1 (0..255), B row rB = tid>>1 (<128)
    const int rA = tid >> 1;
    const int hh = tid & 1;

    // warp GEMM role: m-slot (wid&7)*32, n-half (wid>>3)*64
    const int m0base = (wid & 7) * 32;
    const int nbase  = (wid >> 3) * 64;

    float acc[2][8][4];
#pragma unroll
    for (int mi = 0; mi < 2; mi++)
#pragma unroll
        for (int nj = 0; nj < 8; nj++)
#pragma unroll
            for (int q = 0; q < 4; q++) acc[mi][nj][q] = 0.f;

    const __half* gArow = d_ctx2 + (pixbase + rA) * K2;
    const __half* gBrow = d_w2 + ((size_t)i * 128 + rA) * K2;   // valid if rA<128

    // -------- async loader for one K-stage into one SMEM stage -------------
    auto issue_stage = [&](int s, uint32_t stagebase) {
        const int k0 = s * 64;
#pragma unroll
        for (int q = 0; q < 4; q++) {
            int qq = hh * 4 + q;
            int koff = k0 + qq * 8;          // channel offset of this 16B quad
            if (koff < Kp) {
                uint32_t so = SW128((uint32_t)(rA * 128 + qq * 16));
                CP_ASYNC16(stagebase + OFF_A + so, (const char*)(gArow + koff));
                if (tid < 256)
                    CP_ASYNC16(stagebase + OFF_B + so, (const char*)(gBrow + koff));
            }
        }
        CP_COMMIT();
    };

    issue_stage(0, sb + SM_T0);

    for (int s = 0; s < nstages; s++) {
        const uint32_t cur = sb + SM_T0 + (uint32_t)(s & 1) * STAGE_SZ;
        if (s + 1 < nstages) {
            issue_stage(s + 1, sb + SM_T0 + (uint32_t)((s + 1) & 1) * STAGE_SZ);
            CP_WAIT(1);
        } else {
            CP_WAIT(0);
        }
        __syncthreads();

        const uint32_t sA = cur + OFF_A;
        const uint32_t sB = cur + OFF_B;
        const int chunks = min(4, nchunks - s * 4);

        for (int k = 0; k < chunks; k++) {
            const int kb = k * 32;
            uint32_t afr[2][4];
#pragma unroll
            for (int mi = 0; mi < 2; mi++) {
                uint32_t row = m0base + mi * 16 + (lid & 15);
                uint32_t so = SW128(row * 128 + kb + (lid >> 4) * 16);
                ldsm_x4(afr[mi], sA + so);
            }
            uint32_t bfr[4][4];
#pragma unroll
            for (int nj2 = 0; nj2 < 4; nj2++) {
                uint32_t row = nbase + nj2 * 16 + ((lid >> 4) << 3) + (lid & 7);
                uint32_t so = SW128(row * 128 + kb + ((lid >> 3) & 1) * 16);
                ldsm_x4(bfr[nj2], sB + so);
            }
#pragma unroll
            for (int mi = 0; mi < 2; mi++)
#pragma unroll
                for (int nj = 0; nj < 8; nj++)
                    mma_f16(acc[mi][nj], afr[mi], &bfr[nj >> 1][(nj & 1) * 2]);
        }
        __syncthreads();
    }

    // ---- epilogue: bias + relu + dense + cross-half reduce + d2s ----------
    const float* bcs = (const float*)(smem + SM_BCS);
    const float* wds = (const float*)(smem + SM_WDS);
    float* red = (float*)(smem + SM_RED);          // 256 floats

    float rs[2][2];
#pragma unroll
    for (int mi = 0; mi < 2; mi++) {
#pragma unroll
        for (int h = 0; h < 2; h++) {
            float s = 0.f;
#pragma unroll
            for (int nj = 0; nj < 8; nj++) {
                int n = nbase + nj * 8 + 2 * (lid & 3);
                float v0 = acc[mi][nj][h * 2 + 0] + bcs[n];
                float v1 = acc[mi][nj][h * 2 + 1] + bcs[n + 1];
                v0 = fmaxf(v0, 0.f);
                v1 = fmaxf(v1, 0.f);
                s = fmaf(v0, wds[n], s);
                s = fmaf(v1, wds[n + 1], s);
            }
            s += __shfl_xor_sync(0xffffffffu, s, 1);
            s += __shfl_xor_sync(0xffffffffu, s, 2);
            rs[mi][h] = s;
        }
    }
    if ((wid >> 3) == 1 && (lid & 3) == 0) {
#pragma unroll
        for (int mi = 0; mi < 2; mi++)
#pragma unroll
            for (int h = 0; h < 2; h++)
                red[m0base + mi * 16 + h * 8 + (lid >> 2)] = rs[mi][h];
    }
    __syncthreads();
    if ((wid >> 3) == 0 && (lid & 3) == 0) {
        const float bdv = bd[i];
        const int rr  = i / 12;
        const int ss2 = (i / 3) & 3;
        const int chn = i % 3;
#pragma unroll
        for (int mi = 0; mi < 2; mi++)
#pragma unroll
            for (int h = 0; h < 2; h++) {
                int row = m0base + mi * 16 + h * 8 + (lid >> 2);
                float s = rs[mi][h] + red[row];
                int ppy = row >> 6;                // 0..3 within tile
                int ppx = row & 63;
                float val = (s + bdv) * 0.5f + 0.5f;
                out[(((size_t)b * 256 + (y0 + ppy) * 4 + rr) * 256 +
                     (ppx * 4 + ss2)) * 3 + chn] = val;
            }
    }
}

// ---------------------------------------------------------------------------
extern "C" void kernel_launch(void* const* d_in, const int* in_sizes, int n_in,
                              void* d_out, int out_size) {
    const float* ex = (const float*)d_in[0];  // (8,266,266,3)
    const float* Wc = (const float*)d_in[1];  // (48,3,3,59,128)
    const float* bc = (const float*)d_in[2];  // (48,128)
    const float* Wd = (const float*)d_in[3];  // (48,128,1)
    const float* bd = (const float*)d_in[4];  // (48,1)
    float* out = (float*)d_out;               // (8,256,256,3)

    initCoefsK<<<1, 32>>>();

    const int nG = 8 * 266 * 266 * 3;
    gammaK<<<(nG + 255) / 256, 256>>>(ex, nG);

    const int nH = 8 * 128 * 266 * 3;
    convHK<<<(nH + 255) / 256, 256>>>();

    const int nZ4 = (8 * CTX_H * CTX_W * CTX_C) / 4;
    zeroCtxK<<<(nZ4 + 255) / 256, 256>>>();

    const int nW = 8 * 128 * 128 * 3;
    convWK<<<(nW + 255) / 256, 256>>>();

    const int nE = 8 * 256 * 256 * 3;
    exCropK<<<(nE + 255) / 256, 256>>>(ex);

    ctx2K<<<8 * 64 * 64 / 4, 256>>>();   // 4 pixels per block, 8192 blocks

    const size_t nW2 = (size_t)48 * 128 * K2;
    w2K<<<(unsigned)((nW2 + 255) / 256), 256>>>(Wc);

    cudaFuncSetAttribute(predMmaK, cudaFuncAttributeMaxDynamicSharedMemorySize,
                         SM_TOTAL);
    dim3 grid(128, 48);                  // 128 tiles (8 b x 16 ty), 48 preds
    predMmaK<<<grid, 512, SM_TOTAL>>>(bc, Wd, bd, out);
}

// round 16
// speedup vs baseline: 1.0490x; 1.0490x over previous
#include <cuda_runtime.h>
#include <cuda_fp16.h>
#include <math.h>
#include <stdint.h>

// ---------------------------------------------------------------------------
// Scale_41523743817857 — fp16 mma.sync with nested-prefix im2col K-packing.
// prepA {coefs | gamma | w2K} -> prepB {convH | zeroCtx} -> prepC {convW |
// exCrop} -> ctx2K-lite (one-smem-hop im2col, ch2 = ch*9+tap nested-prefix
// order) -> predMmaK: one GEMM per (i, 128-px tile), M=128 N=128
// K=ceil(9c/16)*16, 2-stage cp.async pipeline, m16n8k16 fp16 MMAs + fp32
// accumulators, fused bias+relu+dense+depth_to_space epilogue.
// Grid (256, 48) x-major: concurrent CTAs share predictor B-tiles in L2.
// ---------------------------------------------------------------------------

#define CTX_H 66
#define CTX_W 66
#define CTX_C 64
#define K2    592          // padded im2col channel count (>= max Kp = 544)

__device__ float d_g[8 * 266 * 266 * 3];
__device__ float d_t1[8 * 128 * 266 * 3];
__device__ float d_kc[12];
__device__ __half d_ctxf[8 * CTX_H * CTX_W * CTX_C];   // fp16 padded context
__device__ __half d_ctx2[8 * 64 * 64 * K2];            // im2col, (ch*9+tap) order
__device__ __half d_w2[48 * 128 * K2];                 // weights, same order

#define SW128(o) ((o) ^ (((o) >> 3) & 0x70))

__device__ __forceinline__ uint32_t smem_to_u32(const void* p) {
    uint32_t a;
    asm("{ .reg .u64 t; cvta.to.shared.u64 t, %1; cvt.u32.u64 %0, t; }"
        : "=r"(a) : "l"(p));
    return a;
}
__device__ __forceinline__ void ldsm_x4(uint32_t* r, uint32_t addr) {
    asm volatile("ldmatrix.sync.aligned.m8n8.x4.shared.b16 {%0,%1,%2,%3}, [%4];"
        : "=r"(r[0]), "=r"(r[1]), "=r"(r[2]), "=r"(r[3]) : "r"(addr));
}
__device__ __forceinline__ void mma_f16(float* c, const uint32_t* a,
                                        const uint32_t* b) {
    asm volatile(
        "mma.sync.aligned.m16n8k16.row.col.f32.f16.f16.f32 "
        "{%0,%1,%2,%3}, {%4,%5,%6,%7}, {%8,%9}, {%0,%1,%2,%3};"
        : "+f"(c[0]), "+f"(c[1]), "+f"(c[2]), "+f"(c[3])
        : "r"(a[0]), "r"(a[1]), "r"(a[2]), "r"(a[3]), "r"(b[0]), "r"(b[1]));
}
#define CP_ASYNC16(dst, src) \
    asm volatile("cp.async.cg.shared.global [%0], [%1], 16;" \
        :: "r"(dst), "l"(src) : "memory")
#define CP_COMMIT() asm volatile("cp.async.commit_group;" ::: "memory")
#define CP_WAIT(n)  asm volatile("cp.async.wait_group %0;" :: "n"(n) : "memory")

// ======================= device-side stage bodies ==========================
__device__ __forceinline__ void body_coefs() {
    double v[12]; double sum = 0.0;
    for (int t = 0; t < 12; t++) {
        double pos = ((double)t - 5.5) / 2.0;
        double a = sin(M_PI * pos) / (M_PI * pos);
        double p3 = pos / 3.0;
        double b = sin(M_PI * p3) / (M_PI * p3);
        double val = (double)((float)(a * b));
        v[t] = val; sum += val;
    }
    for (int t = 0; t < 12; t++) d_kc[t] = (float)(v[t] / sum);
}
__device__ __forceinline__ void body_w2(const float* __restrict__ Wc, size_t idx) {
    int ch2 = (int)(idx % K2);
    int nn  = (int)((idx / K2) % 128);
    int i   = (int)(idx / ((size_t)K2 * 128));
    int c   = 12 + i;
    float v = 0.f;
    if (ch2 < 576) {
        int ch  = ch2 / 9;
        int tap = ch2 - ch * 9;
        if (ch < c)
            v = Wc[((((size_t)i * 3 + tap / 3) * 3 + (tap % 3)) * 59 + ch) * 128 + nn];
    }
    d_w2[idx] = __float2half_rn(v);
}
__device__ __forceinline__ void body_convH(int idx) {
    float k[12];
#pragma unroll
    for (int t = 0; t < 12; t++) k[t] = d_kc[t];
    int ch = idx % 3;
    int w  = (idx / 3) % 266;
    int h  = (idx / (3 * 266)) % 128;
    int b  = idx / (3 * 266 * 128);
    const float* src = d_g + ((size_t)(b * 266 + 2 * h) * 266 + w) * 3 + ch;
    float s = 0.f;
#pragma unroll
    for (int t = 0; t < 12; t++) s += k[t] * src[(size_t)t * 266 * 3];
    d_t1[idx] = s;
}
__device__ __forceinline__ void body_convW(int idx) {
    float k[12];
#pragma unroll
    for (int t = 0; t < 12; t++) k[t] = d_kc[t];
    int ch = idx % 3;
    int w2 = (idx / 3) % 128;
    int h  = (idx / (3 * 128)) % 128;
    int b  = idx / (3 * 128 * 128);
    const float* src = d_t1 + ((size_t)(b * 128 + h) * 266 + 2 * w2) * 3 + ch;
    float s = 0.f;
#pragma unroll
    for (int t = 0; t < 12; t++) s += k[t] * src[t * 3];
    float v = (s > 0.f) ? __powf(fmaxf(s, 1e-20f), (float)(1.0 / 2.2)) : 0.f;
    v = v * 2.f - 1.f;
    int yo = h >> 1, xo = w2 >> 1;
    int sub = ((h & 1) * 2 + (w2 & 1)) * 3 + ch;
    d_ctxf[(((size_t)b * CTX_H + 1 + yo) * CTX_W + 1 + xo) * CTX_C + sub] =
        __float2half_rn(v);
}
__device__ __forceinline__ void body_exCrop(const float* __restrict__ ex, int idx) {
    int ch = idx % 3;
    int x  = (idx / 3) % 256;
    int y  = (idx / (3 * 256)) % 256;
    int b  = idx / (3 * 256 * 256);
    float v = ex[((size_t)(b * 266 + 5 + y) * 266 + (5 + x)) * 3 + ch] * 2.f - 1.f;
    int yo = y >> 2, xo = x >> 2;
    int sub = 12 + ((y & 3) * 4 + (x & 3)) * 3 + ch;
    d_ctxf[(((size_t)b * CTX_H + 1 + yo) * CTX_W + 1 + xo) * CTX_C + sub] =
        __float2half_rn(v);
}

// ======================= fused preprocessing launches ======================
#define N_GAMMA   (8 * 266 * 266 * 3)
#define NB_GAMMA  ((N_GAMMA + 255) / 256)
#define N_W2      (48 * 128 * K2)
#define NB_W2     ((N_W2 + 255) / 256)
#define NB_PREPA  (NB_GAMMA + 1 + NB_W2)

__global__ void prepAK(const float* __restrict__ x, const float* __restrict__ Wc) {
    int bx = blockIdx.x;
    if (bx < NB_GAMMA) {
        int i = bx * 256 + threadIdx.x;
        if (i < N_GAMMA) d_g[i] = __powf(x[i], 2.2f);
    } else if (bx == NB_GAMMA) {
        if (threadIdx.x == 0) body_coefs();
    } else {
        size_t idx = (size_t)(bx - NB_GAMMA - 1) * 256 + threadIdx.x;
        if (idx < (size_t)N_W2) body_w2(Wc, idx);
    }
}

#define N_CONVH   (8 * 128 * 266 * 3)
#define NB_CONVH  ((N_CONVH + 255) / 256)
#define N_ZERO4   ((8 * CTX_H * CTX_W * CTX_C) / 4)
#define NB_ZERO   ((N_ZERO4 + 255) / 256)
#define NB_PREPB  (NB_CONVH + NB_ZERO)

__global__ void prepBK() {
    int bx = blockIdx.x;
    if (bx < NB_CONVH) {
        int idx = bx * 256 + threadIdx.x;
        if (idx < N_CONVH) body_convH(idx);
    } else {
        int i = (bx - NB_CONVH) * 256 + threadIdx.x;
        if (i < N_ZERO4) ((uint2*)d_ctxf)[i] = make_uint2(0u, 0u);
    }
}

#define N_CONVW   (8 * 128 * 128 * 3)
#define NB_CONVW  ((N_CONVW + 255) / 256)
#define N_EXC     (8 * 256 * 256 * 3)
#define NB_EXC    ((N_EXC + 255) / 256)
#define NB_PREPC  (NB_CONVW + NB_EXC)

__global__ void prepCK(const float* __restrict__ ex) {
    int bx = blockIdx.x;
    if (bx < NB_CONVW) {
        int idx = bx * 256 + threadIdx.x;
        if (idx < N_CONVW) body_convW(idx);
    } else {
        int idx = (bx - NB_CONVW) * 256 + threadIdx.x;
        if (idx < N_EXC) body_exCrop(ex, idx);
    }
}

// im2col lite: thread = (pixel, ch); 9 coalesced L2-cached gmem loads per
// thread, scatter into a per-pixel smem row buffer (writes only), then flush
// 4 complete 592-ch rows with coalesced uint4 stores. One smem hop.
#define SROW_STRIDE 600    // halves; 1200 B, 16B-aligned
__global__ __launch_bounds__(256) void ctx2K() {
    __shared__ __half srow[4 * SROW_STRIDE];
    const int tid = threadIdx.x;
    const int ch  = tid & 63;
    const int pl  = tid >> 6;               // 0..3
    const int pix = blockIdx.x * 4 + pl;
    const int x = pix & 63;
    const int y = (pix >> 6) & 63;
    const int b = pix >> 12;

    const __half* src =
        d_ctxf + (((size_t)b * CTX_H + y) * CTX_W + x) * CTX_C + ch;
    __half* dst = srow + pl * SROW_STRIDE + ch * 9;
#pragma unroll
    for (int ky = 0; ky < 3; ky++)
#pragma unroll
        for (int kx = 0; kx < 3; kx++)
            dst[ky * 3 + kx] = src[((size_t)ky * CTX_W + kx) * CTX_C];
    if (ch < 16)
        srow[pl * SROW_STRIDE + 576 + ch] = __ushort_as_half(0);
    __syncthreads();

    // flush: 4 rows x 74 uint4 (592 halves)
    for (int t = tid; t < 4 * 74; t += 256) {
        int p2 = t / 74;
        int q  = t - p2 * 74;
        *(uint4*)(d_ctx2 + ((size_t)(blockIdx.x * 4 + p2)) * K2 + q * 8) =
            *(const uint4*)(srow + p2 * SROW_STRIDE + q * 8);
    }
}

// ======================= main tensor-core kernel ===========================
// SMEM: RED/BCS/WDS then two 32KB stages of {A, B} 16KB fp16 tiles (K=64 each).
#define SM_RED   0
#define SM_BCS   512
#define SM_WDS   1024
#define SM_T0    2048
#define OFF_A    0
#define OFF_B    16384
#define STAGE_SZ 32768
#define SM_TOTAL (SM_T0 + 2 * STAGE_SZ)   // 67584 B

__global__ __launch_bounds__(256, 2) void predMmaK(
    const float* __restrict__ bc,   // (48,128)
    const float* __restrict__ Wd,   // (48,128)
    const float* __restrict__ bd,   // (48)
    float* __restrict__ out)        // (8,256,256,3)
{
    extern __shared__ char smem[];
    uint32_t sb = smem_to_u32(smem);
    const int tid = threadIdx.x;
    const int wid = tid >> 5;
    const int lid = tid & 31;

    const int i = blockIdx.y;
    const int c = 12 + i;
    const int Kp = ((9 * c + 15) >> 4) << 4;   // packed K, mult of 16
    const int nchunks = Kp >> 4;               // 7..34
    const int nstages = (nchunks + 3) >> 2;    // K=64 stages

    const int tile = blockIdx.x;               // b in [0,8), ty in [0,32)
    const int b  = tile >> 5;
    const int ty = tile & 31;
    const int y0 = ty * 2;
    const size_t pixbase = (size_t)b * 4096 + (size_t)y0 * 64;  // 128 linear px

    if (tid < 128) {
        ((float*)(smem + SM_BCS))[tid] = bc[i * 128 + tid];
        ((float*)(smem + SM_WDS))[tid] = Wd[i * 128 + tid];
    }

    // tile-load role: row r, 64B half hh (quads qq = hh*4..hh*4+3)
    const int r  = tid >> 1;
    const int hh = tid & 1;

    // warp GEMM role
    const int m0base = (wid & 3) * 32;
    const int nbase  = (wid >> 2) * 64;

    float acc[2][8][4];
#pragma unroll
    for (int mi = 0; mi < 2; mi++)
#pragma unroll
        for (int nj = 0; nj < 8; nj++)
#pragma unroll
            for (int q = 0; q < 4; q++) acc[mi][nj][q] = 0.f;

    const __half* gArow = d_ctx2 + (pixbase + r) * K2;
    const __half* gBrow = d_w2 + ((size_t)i * 128 + r) * K2;

    // -------- async loader for one K-stage into one SMEM stage -------------
    auto issue_stage = [&](int s, uint32_t stagebase) {
        const int k0 = s * 64;
#pragma unroll
        for (int q = 0; q < 4; q++) {
            int qq = hh * 4 + q;
            int koff = k0 + qq * 8;          // channel offset of this 16B quad
            if (koff < Kp) {
                uint32_t so = SW128((uint32_t)(r * 128 + qq * 16));
                CP_ASYNC16(stagebase + OFF_A + so, (const char*)(gArow + koff));
                CP_ASYNC16(stagebase + OFF_B + so, (const char*)(gBrow + koff));
            }
        }
        CP_COMMIT();
    };

    issue_stage(0, sb + SM_T0);

    for (int s = 0; s < nstages; s++) {
        const uint32_t cur = sb + SM_T0 + (uint32_t)(s & 1) * STAGE_SZ;
        if (s + 1 < nstages) {
            issue_stage(s + 1, sb + SM_T0 + (uint32_t)((s + 1) & 1) * STAGE_SZ);
            CP_WAIT(1);
        } else {
            CP_WAIT(0);
        }
        __syncthreads();

        const uint32_t sA = cur + OFF_A;
        const uint32_t sB = cur + OFF_B;
        const int chunks = min(4, nchunks - s * 4);

        for (int k = 0; k < chunks; k++) {
            const int kb = k * 32;
            uint32_t afr[2][4];
#pragma unroll
            for (int mi = 0; mi < 2; mi++) {
                uint32_t row = m0base + mi * 16 + (lid & 15);
                uint32_t so = SW128(row * 128 + kb + (lid >> 4) * 16);
                ldsm_x4(afr[mi], sA + so);
            }
            uint32_t bfr[4][4];
#pragma unroll
            for (int nj2 = 0; nj2 < 4; nj2++) {
                uint32_t row = nbase + nj2 * 16 + ((lid >> 4) << 3) + (lid & 7);
                uint32_t so = SW128(row * 128 + kb + ((lid >> 3) & 1) * 16);
                ldsm_x4(bfr[nj2], sB + so);
            }
#pragma unroll
            for (int mi = 0; mi < 2; mi++)
#pragma unroll
                for (int nj = 0; nj < 8; nj++)
                    mma_f16(acc[mi][nj], afr[mi], &bfr[nj >> 1][(nj & 1) * 2]);
        }
        __syncthreads();
    }

    // ---- epilogue: bias + relu + dense + cross-half reduce + d2s ----------
    const float* bcs = (const float*)(smem + SM_BCS);
    const float* wds = (const float*)(smem + SM_WDS);
    float* red = (float*)(smem + SM_RED);

    float rs[2][2];
#pragma unroll
    for (int mi = 0; mi < 2; mi++) {
#pragma unroll
        for (int h = 0; h < 2; h++) {
            float s = 0.f;
#pragma unroll
            for (int nj = 0; nj < 8; nj++) {
                int n = nbase + nj * 8 + 2 * (lid & 3);
                float v0 = acc[mi][nj][h * 2 + 0] + bcs[n];
                float v1 = acc[mi][nj][h * 2 + 1] + bcs[n + 1];
                v0 = fmaxf(v0, 0.f);
                v1 = fmaxf(v1, 0.f);
                s = fmaf(v0, wds[n], s);
                s = fmaf(v1, wds[n + 1], s);
            }
            s += __shfl_xor_sync(0xffffffffu, s, 1);
            s += __shfl_xor_sync(0xffffffffu, s, 2);
            rs[mi][h] = s;
        }
    }
    if ((wid >> 2) == 1 && (lid & 3) == 0) {
#pragma unroll
        for (int mi = 0; mi < 2; mi++)
#pragma unroll
            for (int h = 0; h < 2; h++)
                red[m0base + mi * 16 + h * 8 + (lid >> 2)] = rs[mi][h];
    }
    __syncthreads();
    if ((wid >> 2) == 0 && (lid & 3) == 0) {
        const float bdv = bd[i];
        const int rr  = i / 12;
        const int ss2 = (i / 3) & 3;
        const int chn = i % 3;
#pragma unroll
        for (int mi = 0; mi < 2; mi++)
#pragma unroll
            for (int h = 0; h < 2; h++) {
                int row = m0base + mi * 16 + h * 8 + (lid >> 2);
                float s = rs[mi][h] + red[row];
                int ppy = row >> 6;
                int ppx = row & 63;
                float val = (s + bdv) * 0.5f + 0.5f;
                out[(((size_t)b * 256 + (y0 + ppy) * 4 + rr) * 256 +
                     (ppx * 4 + ss2)) * 3 + chn] = val;
            }
    }
}

// ---------------------------------------------------------------------------
extern "C" void kernel_launch(void* const* d_in, const int* in_sizes, int n_in,
                              void* d_out, int out_size) {
    const float* ex = (const float*)d_in[0];  // (8,266,266,3)
    const float* Wc = (const float*)d_in[1];  // (48,3,3,59,128)
    const float* bc = (const float*)d_in[2];  // (48,128)
    const float* Wd = (const float*)d_in[3];  // (48,128,1)
    const float* bd = (const float*)d_in[4];  // (48,1)
    float* out = (float*)d_out;               // (8,256,256,3)

    prepAK<<<NB_PREPA, 256>>>(ex, Wc);   // coefs | gamma | weight reorder
    prepBK<<<NB_PREPB, 256>>>();         // convH | zero ctx
    prepCK<<<NB_PREPC, 256>>>(ex);       // convW | example crop

    ctx2K<<<8 * 64 * 64 / 4, 256>>>();   // 4 pixels per block, 8192 blocks

    cudaFuncSetAttribute(predMmaK, cudaFuncAttributeMaxDynamicSharedMemorySize,
                         SM_TOTAL);
    dim3 grid(256, 48);                  // x-major: B-tile L2 sharing
    predMmaK<<<grid, 256, SM_TOTAL>>>(bc, Wd, bd, out);
}

// round 17
// speedup vs baseline: 1.0732x; 1.0230x over previous
#include <cuda_runtime.h>
#include <cuda_fp16.h>
#include <math.h>
#include <stdint.h>

// ---------------------------------------------------------------------------
// Scale_41523743817857 — fp16 mma.sync with nested-prefix im2col K-packing.
// prepA {coefs | gamma | w2K} -> prepB {convH | zeroCtx} -> prepC {convW |
// exCrop} -> ctx2K-lite (one-smem-hop im2col, ch2 = ch*9+tap nested-prefix
// order) -> predMmaK: one GEMM per (i, 128-px tile), M=128 N=128
// K=ceil(9c/16)*16, 3-stage single-barrier cp.async pipeline, m16n8k16 fp16
// MMAs + fp32 accumulators, fused bias+relu+dense+depth_to_space epilogue.
// Grid (256, 48) x-major: concurrent CTAs share predictor B-tiles in L2.
// ---------------------------------------------------------------------------

#define CTX_H 66
#define CTX_W 66
#define CTX_C 64
#define K2    592          // padded im2col channel count (>= max Kp = 544)

__device__ float d_g[8 * 266 * 266 * 3];
__device__ float d_t1[8 * 128 * 266 * 3];
__device__ float d_kc[12];
__device__ __half d_ctxf[8 * CTX_H * CTX_W * CTX_C];   // fp16 padded context
__device__ __half d_ctx2[8 * 64 * 64 * K2];            // im2col, (ch*9+tap) order
__device__ __half d_w2[48 * 128 * K2];                 // weights, same order

#define SW128(o) ((o) ^ (((o) >> 3) & 0x70))

__device__ __forceinline__ uint32_t smem_to_u32(const void* p) {
    uint32_t a;
    asm("{ .reg .u64 t; cvta.to.shared.u64 t, %1; cvt.u32.u64 %0, t; }"
        : "=r"(a) : "l"(p));
    return a;
}
__device__ __forceinline__ void ldsm_x4(uint32_t* r, uint32_t addr) {
    asm volatile("ldmatrix.sync.aligned.m8n8.x4.shared.b16 {%0,%1,%2,%3}, [%4];"
        : "=r"(r[0]), "=r"(r[1]), "=r"(r[2]), "=r"(r[3]) : "r"(addr));
}
__device__ __forceinline__ void mma_f16(float* c, const uint32_t* a,
                                        const uint32_t* b) {
    asm volatile(
        "mma.sync.aligned.m16n8k16.row.col.f32.f16.f16.f32 "
        "{%0,%1,%2,%3}, {%4,%5,%6,%7}, {%8,%9}, {%0,%1,%2,%3};"
        : "+f"(c[0]), "+f"(c[1]), "+f"(c[2]), "+f"(c[3])
        : "r"(a[0]), "r"(a[1]), "r"(a[2]), "r"(a[3]), "r"(b[0]), "r"(b[1]));
}
#define CP_ASYNC16(dst, src) \
    asm volatile("cp.async.cg.shared.global [%0], [%1], 16;" \
        :: "r"(dst), "l"(src) : "memory")
#define CP_COMMIT() asm volatile("cp.async.commit_group;" ::: "memory")
#define CP_WAIT(n)  asm volatile("cp.async.wait_group %0;" :: "n"(n) : "memory")

// ======================= device-side stage bodies ==========================
__device__ __forceinline__ void body_coefs() {
    double v[12]; double sum = 0.0;
    for (int t = 0; t < 12; t++) {
        double pos = ((double)t - 5.5) / 2.0;
        double a = sin(M_PI * pos) / (M_PI * pos);
        double p3 = pos / 3.0;
        double b = sin(M_PI * p3) / (M_PI * p3);
        double val = (double)((float)(a * b));
        v[t] = val; sum += val;
    }
    for (int t = 0; t < 12; t++) d_kc[t] = (float)(v[t] / sum);
}
__device__ __forceinline__ void body_w2(const float* __restrict__ Wc, size_t idx) {
    int ch2 = (int)(idx % K2);
    int nn  = (int)((idx / K2) % 128);
    int i   = (int)(idx / ((size_t)K2 * 128));
    int c   = 12 + i;
    float v = 0.f;
    if (ch2 < 576) {
        int ch  = ch2 / 9;
        int tap = ch2 - ch * 9;
        if (ch < c)
            v = Wc[((((size_t)i * 3 + tap / 3) * 3 + (tap % 3)) * 59 + ch) * 128 + nn];
    }
    d_w2[idx] = __float2half_rn(v);
}
__device__ __forceinline__ void body_convH(int idx) {
    float k[12];
#pragma unroll
    for (int t = 0; t < 12; t++) k[t] = d_kc[t];
    int ch = idx % 3;
    int w  = (idx / 3) % 266;
    int h  = (idx / (3 * 266)) % 128;
    int b  = idx / (3 * 266 * 128);
    const float* src = d_g + ((size_t)(b * 266 + 2 * h) * 266 + w) * 3 + ch;
    float s = 0.f;
#pragma unroll
    for (int t = 0; t < 12; t++) s += k[t] * src[(size_t)t * 266 * 3];
    d_t1[idx] = s;
}
__device__ __forceinline__ void body_convW(int idx) {
    float k[12];
#pragma unroll
    for (int t = 0; t < 12; t++) k[t] = d_kc[t];
    int ch = idx % 3;
    int w2 = (idx / 3) % 128;
    int h  = (idx / (3 * 128)) % 128;
    int b  = idx / (3 * 128 * 128);
    const float* src = d_t1 + ((size_t)(b * 128 + h) * 266 + 2 * w2) * 3 + ch;
    float s = 0.f;
#pragma unroll
    for (int t = 0; t < 12; t++) s += k[t] * src[t * 3];
    float v = (s > 0.f) ? __powf(fmaxf(s, 1e-20f), (float)(1.0 / 2.2)) : 0.f;
    v = v * 2.f - 1.f;
    int yo = h >> 1, xo = w2 >> 1;
    int sub = ((h & 1) * 2 + (w2 & 1)) * 3 + ch;
    d_ctxf[(((size_t)b * CTX_H + 1 + yo) * CTX_W + 1 + xo) * CTX_C + sub] =
        __float2half_rn(v);
}
__device__ __forceinline__ void body_exCrop(const float* __restrict__ ex, int idx) {
    int ch = idx % 3;
    int x  = (idx / 3) % 256;
    int y  = (idx / (3 * 256)) % 256;
    int b  = idx / (3 * 256 * 256);
    float v = ex[((size_t)(b * 266 + 5 + y) * 266 + (5 + x)) * 3 + ch] * 2.f - 1.f;
    int yo = y >> 2, xo = x >> 2;
    int sub = 12 + ((y & 3) * 4 + (x & 3)) * 3 + ch;
    d_ctxf[(((size_t)b * CTX_H + 1 + yo) * CTX_W + 1 + xo) * CTX_C + sub] =
        __float2half_rn(v);
}

// ======================= fused preprocessing launches ======================
#define N_GAMMA   (8 * 266 * 266 * 3)
#define NB_GAMMA  ((N_GAMMA + 255) / 256)
#define N_W2      (48 * 128 * K2)
#define NB_W2     ((N_W2 + 255) / 256)
#define NB_PREPA  (NB_GAMMA + 1 + NB_W2)

__global__ void prepAK(const float* __restrict__ x, const float* __restrict__ Wc) {
    int bx = blockIdx.x;
    if (bx < NB_GAMMA) {
        int i = bx * 256 + threadIdx.x;
        if (i < N_GAMMA) d_g[i] = __powf(x[i], 2.2f);
    } else if (bx == NB_GAMMA) {
        if (threadIdx.x == 0) body_coefs();
    } else {
        size_t idx = (size_t)(bx - NB_GAMMA - 1) * 256 + threadIdx.x;
        if (idx < (size_t)N_W2) body_w2(Wc, idx);
    }
}

#define N_CONVH   (8 * 128 * 266 * 3)
#define NB_CONVH  ((N_CONVH + 255) / 256)
#define N_ZERO4   ((8 * CTX_H * CTX_W * CTX_C) / 4)
#define NB_ZERO   ((N_ZERO4 + 255) / 256)
#define NB_PREPB  (NB_CONVH + NB_ZERO)

__global__ void prepBK() {
    int bx = blockIdx.x;
    if (bx < NB_CONVH) {
        int idx = bx * 256 + threadIdx.x;
        if (idx < N_CONVH) body_convH(idx);
    } else {
        int i = (bx - NB_CONVH) * 256 + threadIdx.x;
        if (i < N_ZERO4) ((uint2*)d_ctxf)[i] = make_uint2(0u, 0u);
    }
}

#define N_CONVW   (8 * 128 * 128 * 3)
#define NB_CONVW  ((N_CONVW + 255) / 256)
#define N_EXC     (8 * 256 * 256 * 3)
#define NB_EXC    ((N_EXC + 255) / 256)
#define NB_PREPC  (NB_CONVW + NB_EXC)

__global__ void prepCK(const float* __restrict__ ex) {
    int bx = blockIdx.x;
    if (bx < NB_CONVW) {
        int idx = bx * 256 + threadIdx.x;
        if (idx < N_CONVW) body_convW(idx);
    } else {
        int idx = (bx - NB_CONVW) * 256 + threadIdx.x;
        if (idx < N_EXC) body_exCrop(ex, idx);
    }
}

// im2col lite: thread = (pixel, ch); 9 coalesced L2-cached gmem loads per
// thread, scatter into a per-pixel smem row buffer (writes only), then flush
// 4 complete 592-ch rows with coalesced uint4 stores. One smem hop.
#define SROW_STRIDE 600    // halves; 1200 B, 16B-aligned
__global__ __launch_bounds__(256) void ctx2K() {
    __shared__ __half srow[4 * SROW_STRIDE];
    const int tid = threadIdx.x;
    const int ch  = tid & 63;
    const int pl  = tid >> 6;               // 0..3
    const int pix = blockIdx.x * 4 + pl;
    const int x = pix & 63;
    const int y = (pix >> 6) & 63;
    const int b = pix >> 12;

    const __half* src =
        d_ctxf + (((size_t)b * CTX_H + y) * CTX_W + x) * CTX_C + ch;
    __half* dst = srow + pl * SROW_STRIDE + ch * 9;
#pragma unroll
    for (int ky = 0; ky < 3; ky++)
#pragma unroll
        for (int kx = 0; kx < 3; kx++)
            dst[ky * 3 + kx] = src[((size_t)ky * CTX_W + kx) * CTX_C];
    if (ch < 16)
        srow[pl * SROW_STRIDE + 576 + ch] = __ushort_as_half(0);
    __syncthreads();

    // flush: 4 rows x 74 uint4 (592 halves)
    for (int t = tid; t < 4 * 74; t += 256) {
        int p2 = t / 74;
        int q  = t - p2 * 74;
        *(uint4*)(d_ctx2 + ((size_t)(blockIdx.x * 4 + p2)) * K2 + q * 8) =
            *(const uint4*)(srow + p2 * SROW_STRIDE + q * 8);
    }
}

// ======================= main tensor-core kernel ===========================
// SMEM: RED/BCS/WDS then THREE 32KB stages of {A, B} 16KB fp16 tiles (K=64).
#define SM_RED   0
#define SM_BCS   512
#define SM_WDS   1024
#define SM_T0    2048
#define OFF_A    0
#define OFF_B    16384
#define STAGE_SZ 32768
#define NSTG     3
#define SM_TOTAL (SM_T0 + NSTG * STAGE_SZ)   // 100352 B (2 CTA/SM: 196 KB)

__global__ __launch_bounds__(256, 2) void predMmaK(
    const float* __restrict__ bc,   // (48,128)
    const float* __restrict__ Wd,   // (48,128)
    const float* __restrict__ bd,   // (48)
    float* __restrict__ out)        // (8,256,256,3)
{
    extern __shared__ char smem[];
    uint32_t sb = smem_to_u32(smem);
    const int tid = threadIdx.x;
    const int wid = tid >> 5;
    const int lid = tid & 31;

    const int i = blockIdx.y;
    const int c = 12 + i;
    const int Kp = ((9 * c + 15) >> 4) << 4;   // packed K, mult of 16
    const int nchunks = Kp >> 4;               // 7..34
    const int nstages = (nchunks + 3) >> 2;    // K=64 stages (2..9)

    const int tile = blockIdx.x;               // b in [0,8), ty in [0,32)
    const int b  = tile >> 5;
    const int ty = tile & 31;
    const int y0 = ty * 2;
    const size_t pixbase = (size_t)b * 4096 + (size_t)y0 * 64;  // 128 linear px

    if (tid < 128) {
        ((float*)(smem + SM_BCS))[tid] = bc[i * 128 + tid];
        ((float*)(smem + SM_WDS))[tid] = Wd[i * 128 + tid];
    }

    // tile-load role: row r, 64B half hh (quads qq = hh*4..hh*4+3)
    const int r  = tid >> 1;
    const int hh = tid & 1;

    // warp GEMM role
    const int m0base = (wid & 3) * 32;
    const int nbase  = (wid >> 2) * 64;

    float acc[2][8][4];
#pragma unroll
    for (int mi = 0; mi < 2; mi++)
#pragma unroll
        for (int nj = 0; nj < 8; nj++)
#pragma unroll
            for (int q = 0; q < 4; q++) acc[mi][nj][q] = 0.f;

    const __half* gArow = d_ctx2 + (pixbase + r) * K2;
    const __half* gBrow = d_w2 + ((size_t)i * 128 + r) * K2;

    // -------- async loader for one K-stage into one SMEM stage -------------
    auto issue_stage = [&](int s, uint32_t stagebase) {
        const int k0 = s * 64;
#pragma unroll
        for (int q = 0; q < 4; q++) {
            int qq = hh * 4 + q;
            int koff = k0 + qq * 8;          // channel offset of this 16B quad
            if (koff < Kp) {
                uint32_t so = SW128((uint32_t)(r * 128 + qq * 16));
                CP_ASYNC16(stagebase + OFF_A + so, (const char*)(gArow + koff));
                CP_ASYNC16(stagebase + OFF_B + so, (const char*)(gBrow + koff));
            }
        }
        CP_COMMIT();
    };

    // prologue: prefetch depth 2 (groups 0, 1)
    issue_stage(0, sb + SM_T0 + 0 * STAGE_SZ);
    if (nstages > 1) issue_stage(1, sb + SM_T0 + 1 * STAGE_SZ);
    else             CP_COMMIT();

    // Single-barrier 3-stage pipeline. Iter s: wait group s (<=1 pending of
    // {s+1}); barrier (proves all warps finished MMA(s-1), so buffer
    // (s+2)%3 == (s-1)%3 is free); issue stage s+2; MMA stage s.
    int sbuf = 0;
    for (int s = 0; s < nstages; s++) {
        CP_WAIT(1);
        __syncthreads();

        if (s + 2 < nstages) {
            int nb2 = sbuf + 2;
            if (nb2 >= NSTG) nb2 -= NSTG;
            issue_stage(s + 2, sb + SM_T0 + (uint32_t)nb2 * STAGE_SZ);
        } else {
            CP_COMMIT();   // keep group numbering uniform
        }

        const uint32_t cur = sb + SM_T0 + (uint32_t)sbuf * STAGE_SZ;
        const uint32_t sA = cur + OFF_A;
        const uint32_t sB = cur + OFF_B;
        const int chunks = min(4, nchunks - s * 4);

        for (int k = 0; k < chunks; k++) {
            const int kb = k * 32;
            uint32_t afr[2][4];
#pragma unroll
            for (int mi = 0; mi < 2; mi++) {
                uint32_t row = m0base + mi * 16 + (lid & 15);
                uint32_t so = SW128(row * 128 + kb + (lid >> 4) * 16);
                ldsm_x4(afr[mi], sA + so);
            }
            uint32_t bfr[4][4];
#pragma unroll
            for (int nj2 = 0; nj2 < 4; nj2++) {
                uint32_t row = nbase + nj2 * 16 + ((lid >> 4) << 3) + (lid & 7);
                uint32_t so = SW128(row * 128 + kb + ((lid >> 3) & 1) * 16);
                ldsm_x4(bfr[nj2], sB + so);
            }
#pragma unroll
            for (int mi = 0; mi < 2; mi++)
#pragma unroll
                for (int nj = 0; nj < 8; nj++)
                    mma_f16(acc[mi][nj], afr[mi], &bfr[nj >> 1][(nj & 1) * 2]);
        }
        if (++sbuf == NSTG) sbuf = 0;
    }
    __syncthreads();   // protect smem (RED region overlaps nothing, but order)

    // ---- epilogue: bias + relu + dense + cross-half reduce + d2s ----------
    const float* bcs = (const float*)(smem + SM_BCS);
    const float* wds = (const float*)(smem + SM_WDS);
    float* red = (float*)(smem + SM_RED);

    float rs[2][2];
#pragma unroll
    for (int mi = 0; mi < 2; mi++) {
#pragma unroll
        for (int h = 0; h < 2; h++) {
            float s = 0.f;
#pragma unroll
            for (int nj = 0; nj < 8; nj++) {
                int n = nbase + nj * 8 + 2 * (lid & 3);
                float v0 = acc[mi][nj][h * 2 + 0] + bcs[n];
                float v1 = acc[mi][nj][h * 2 + 1] + bcs[n + 1];
                v0 = fmaxf(v0, 0.f);
                v1 = fmaxf(v1, 0.f);
                s = fmaf(v0, wds[n], s);
                s = fmaf(v1, wds[n + 1], s);
            }
            s += __shfl_xor_sync(0xffffffffu, s, 1);
            s += __shfl_xor_sync(0xffffffffu, s, 2);
            rs[mi][h] = s;
        }
    }
    if ((wid >> 2) == 1 && (lid & 3) == 0) {
#pragma unroll
        for (int mi = 0; mi < 2; mi++)
#pragma unroll
            for (int h = 0; h < 2; h++)
                red[m0base + mi * 16 + h * 8 + (lid >> 2)] = rs[mi][h];
    }
    __syncthreads();
    if ((wid >> 2) == 0 && (lid & 3) == 0) {
        const float bdv = bd[i];
        const int rr  = i / 12;
        const int ss2 = (i / 3) & 3;
        const int chn = i % 3;
#pragma unroll
        for (int mi = 0; mi < 2; mi++)
#pragma unroll
            for (int h = 0; h < 2; h++) {
                int row = m0base + mi * 16 + h * 8 + (lid >> 2);
                float s = rs[mi][h] + red[row];
                int ppy = row >> 6;
                int ppx = row & 63;
                float val = (s + bdv) * 0.5f + 0.5f;
                out[(((size_t)b * 256 + (y0 + ppy) * 4 + rr) * 256 +
                     (ppx * 4 + ss2)) * 3 + chn] = val;
            }
    }
}

// ---------------------------------------------------------------------------
extern "C" void kernel_launch(void* const* d_in, const int* in_sizes, int n_in,
                              void* d_out, int out_size) {
    const float* ex = (const float*)d_in[0];  // (8,266,266,3)
    const float* Wc = (const float*)d_in[1];  // (48,3,3,59,128)
    const float* bc = (const float*)d_in[2];  // (48,128)
    const float* Wd = (const float*)d_in[3];  // (48,128,1)
    const float* bd = (const float*)d_in[4];  // (48,1)
    float* out = (float*)d_out;               // (8,256,256,3)

    prepAK<<<NB_PREPA, 256>>>(ex, Wc);   // coefs | gamma | weight reorder
    prepBK<<<NB_PREPB, 256>>>();         // convH | zero ctx
    prepCK<<<NB_PREPC, 256>>>(ex);       // convW | example crop

    ctx2K<<<8 * 64 * 64 / 4, 256>>>();   // 4 pixels per block, 8192 blocks

    cudaFuncSetAttribute(predMmaK, cudaFuncAttributeMaxDynamicSharedMemorySize,
                         SM_TOTAL);
    dim3 grid(256, 48);                  // x-major: B-tile L2 sharing
    predMmaK<<<grid, 256, SM_TOTAL>>>(bc, Wd, bd, out);
}